// round 11
// baseline (speedup 1.0000x reference)
#include <cuda_runtime.h>
#include <math.h>

#define NMAX   12000
#define F_IN   10
#define C1     32
#define K1     35
#define K1P    36          // padded stride for s / as (144B, 16B-aligned)
#define K2     18
#define EPSF   1e-15f
#define RED_BLOCKS 100

// ---------------- device scratch (static: zero at module load) ---------------
__device__ __align__(16) float g_degf[NMAX];         // degree count (cleaned in k_s)
__device__ __align__(16) float g_hn [NMAX * C1];     // raw x@W1, then h1 after k_s
__device__ __align__(16) float g_acc[NMAX * C1];     // scatter accumulator (zeroed in k0)
__device__ __align__(16) float g_s  [NMAX * K1P];    // softmax assignments (padded)
__device__ __align__(16) float g_as [NMAX * K1P];    // adj @ s (zeroed per-row in k_s)
__device__ __align__(16) float g_out1[K1 * C1];      // s^T h1   (zeroed in k_s blk0)
__device__ __align__(16) float g_adj1[K1 * K1P];     // s^T a_s  (zeroed in k_s blk0)
__device__ unsigned g_done;                          // k_red completion counter

__device__ __forceinline__ void red4(float* p, float4 v) {
    asm volatile("red.global.add.v4.f32 [%0], {%1,%2,%3,%4};"
                 :: "l"(p), "f"(v.x), "f"(v.y), "f"(v.z), "f"(v.w) : "memory");
}

// ---------------- kernels ----------------------------------------------------

// k0: block-range split. deg-blocks: count in-degree (no dep sync -> overlaps
// prior replay tail; touches only g_degf). h-blocks: raw h = x@W1, acc = 0.
__global__ void k0(const int* __restrict__ col, const float* __restrict__ x,
                   const float* __restrict__ W1, int E, int N, int DEG_BLOCKS) {
    if ((int)blockIdx.x < DEG_BLOCKS) {
        int e = blockIdx.x * blockDim.x + threadIdx.x;
        if (e < E) atomicAdd(&g_degf[col[e]], 1.0f);
        return;
    }
    __shared__ float sW[F_IN * C1];
    for (int j = threadIdx.x; j < F_IN * C1; j += blockDim.x) sW[j] = W1[j];
    __syncthreads();
    cudaGridDependencySynchronize();       // g_hn/g_acc raced by prior replay's k_red
    int t = (blockIdx.x - DEG_BLOCKS) * blockDim.x + threadIdx.x;
    int i = t >> 3;
    int q = (t & 7) << 2;
    if (i >= N) return;
    float xv[F_IN];
    #pragma unroll
    for (int d = 0; d < F_IN; d++) xv[d] = __ldg(&x[i * F_IN + d]);
    float4 v;
    float* vp = (float*)&v;
    #pragma unroll
    for (int j = 0; j < 4; j++) {
        float a = 0.f;
        #pragma unroll
        for (int d = 0; d < F_IN; d++) a = fmaf(xv[d], sW[d * C1 + q + j], a);
        vp[j] = a;                          // RAW (no dis scaling)
    }
    *(float4*)&g_hn [i * C1 + q] = v;
    *(float4*)&g_acc[i * C1 + q] = make_float4(0.f, 0.f, 0.f, 0.f);
}

// acc[col] += dis[row]*h[row] per edge: 8 threads/edge, leader computes dis.
__global__ void k_agg(const int* __restrict__ row, const int* __restrict__ col, int E) {
    int t = blockIdx.x * blockDim.x + threadIdx.x;
    int e = t >> 3;
    int q = (t & 7) << 2;
    int r = 0, c = 0;
    if (e < E) { r = __ldg(&row[e]); c = __ldg(&col[e]); }
    cudaGridDependencySynchronize();
    float d = 0.f;
    if ((threadIdx.x & 7) == 0 && e < E) d = rsqrtf(g_degf[r] + 1.0f);
    d = __shfl_sync(0xffffffffu, d, (threadIdx.x & 31) & ~7);
    if (e >= E) return;
    float4 v = *(const float4*)&g_hn[r * C1 + q];
    v.x *= d; v.y *= d; v.z *= d; v.w *= d;
    red4(&g_acc[c * C1 + q], v);
}

// h1 = relu(dis*acc + dis^2*h_raw + b1); s = softmax(h1 @ pW1 + pb1). WARP/NODE.
// Also zeroes g_as row, g_degf (self-clean), and out1/adj1 (block 0).
__global__ void k_s(const float* __restrict__ pW1, const float* __restrict__ pb1,
                    const float* __restrict__ b1, int N) {
    __shared__ float sW[C1 * K1P];     // padded: col 35 = 0
    __shared__ float sb[K1P];          // pad bias = -1e30
    __shared__ float sb1[C1];
    for (int j = threadIdx.x; j < C1 * K1P; j += blockDim.x) {
        int f = j / K1P, k = j - f * K1P;
        sW[j] = (k < K1) ? pW1[f * K1 + k] : 0.f;
    }
    if (threadIdx.x < K1P) sb[threadIdx.x] = (threadIdx.x < K1) ? pb1[threadIdx.x] : -1e30f;
    if (threadIdx.x < C1)  sb1[threadIdx.x] = b1[threadIdx.x];
    __syncthreads();
    cudaGridDependencySynchronize();
    if (blockIdx.x == 0) {             // zero pooled targets (consumed 1-2 kernels later)
        for (int j = threadIdx.x; j < K1 * C1;  j += blockDim.x) g_out1[j] = 0.f;
        for (int j = threadIdx.x; j < K1 * K1P; j += blockDim.x) g_adj1[j] = 0.f;
    }
    const int lane = threadIdx.x & 31;
    const int i = (blockIdx.x * blockDim.x + threadIdx.x) >> 5;
    if (i >= N) return;
    if (lane < 9) *(float4*)&g_as[i * K1P + (lane << 2)] =
        make_float4(0.f, 0.f, 0.f, 0.f);
    float dis = 0.f;
    if (lane == 0) {
        dis = rsqrtf(g_degf[i] + 1.0f);
        g_degf[i] = 0.f;               // self-clean for next replay
    }
    dis = __shfl_sync(0xffffffffu, dis, 0);
    float acc  = g_acc[i * C1 + lane];
    float hraw = g_hn [i * C1 + lane];
    float hv = fmaxf(fmaf(dis, acc, fmaf(dis * dis, hraw, sb1[lane])), 0.f);
    g_hn[i * C1 + lane] = hv;          // h1
    const int k1 = 32 + (lane & 3);
    float lg0 = sb[lane];
    float lg1 = sb[k1];
    #pragma unroll
    for (int f = 0; f < C1; f++) {
        float hf = __shfl_sync(0xffffffffu, hv, f);
        lg0 = fmaf(hf, sW[f * K1P + lane], lg0);
        lg1 = fmaf(hf, sW[f * K1P + k1],  lg1);
    }
    float m = fmaxf(lg0, lg1);
    #pragma unroll
    for (int o = 16; o; o >>= 1) m = fmaxf(m, __shfl_xor_sync(0xffffffffu, m, o));
    float e0 = expf(lg0 - m);
    float e1 = expf(lg1 - m);
    float ssum = e0 + ((lane < 4) ? e1 : 0.f);
    #pragma unroll
    for (int o = 16; o; o >>= 1) ssum += __shfl_xor_sync(0xffffffffu, ssum, o);
    float inv = 1.f / ssum;
    g_s[i * K1P + lane] = e0 * inv;
    if (lane < 4) g_s[i * K1P + 32 + lane] = e1 * inv;   // lane3 -> pad col = 0
}

// k_as: block-range split.
//   blocks [0, AB): a_s[row] += s[col], 9 threads/edge.
//   blocks [AB, AB+RED_BLOCKS): out1 = s^T h1 partials (independent of g_as).
__global__ void k_as(const int* __restrict__ row, const int* __restrict__ col,
                     int E, int N, int AB) {
    cudaGridDependencySynchronize();
    if ((int)blockIdx.x < AB) {
        int t = blockIdx.x * blockDim.x + threadIdx.x;
        int e = t / 9;
        int q = (t - e * 9) << 2;
        if (e >= E) return;
        int r = __ldg(&row[e]);
        int c = __ldg(&col[e]);
        float4 v = *(const float4*)&g_s[c * K1P + q];
        red4(&g_as[r * K1P + q], v);
    } else {
        const int tid = threadIdx.x;
        if (tid >= K1 * 8) return;     // 280 live lanes
        const int k  = tid >> 3;
        const int off = (tid & 7) << 2;
        int cb = blockIdx.x - AB;
        int per = (N + RED_BLOCKS - 1) / RED_BLOCKS;
        int n0 = cb * per;
        int n1 = min(n0 + per, N);
        float4 acc = make_float4(0.f, 0.f, 0.f, 0.f);
        for (int n = n0; n < n1; n++) {
            float sv = __ldg(&g_s[n * K1P + k]);
            float4 v = *(const float4*)&g_hn[n * C1 + off];
            acc.x = fmaf(sv, v.x, acc.x);
            acc.y = fmaf(sv, v.y, acc.y);
            acc.z = fmaf(sv, v.z, acc.z);
            acc.w = fmaf(sv, v.w, acc.w);
        }
        red4(&g_out1[k * C1 + off], acc);
    }
}

// adj1 = s^T as partials; LAST block runs the whole post-pool finale inline.
__global__ void k_red(int N,
                      const float* __restrict__ W2,  const float* __restrict__ b2,
                      const float* __restrict__ pW2, const float* __restrict__ pb2,
                      const float* __restrict__ W3,  const float* __restrict__ b3,
                      const float* __restrict__ l1W, const float* __restrict__ l1b,
                      const float* __restrict__ l2W, const float* __restrict__ l2b,
                      float* __restrict__ out) {
    cudaGridDependencySynchronize();
    const int tid = threadIdx.x;
    const int NT  = blockDim.x;
    if (tid < K1 * 9) {                // 315 live lanes
        const int k  = tid / 9;
        const int off = (tid - k * 9) << 2;
        int per = (N + gridDim.x - 1) / gridDim.x;
        int n0 = blockIdx.x * per;
        int n1 = min(n0 + per, N);
        float4 acc = make_float4(0.f, 0.f, 0.f, 0.f);
        for (int n = n0; n < n1; n++) {
            float sv = __ldg(&g_s[n * K1P + k]);
            float4 v = *(const float4*)&g_as[n * K1P + off];
            acc.x = fmaf(sv, v.x, acc.x);
            acc.y = fmaf(sv, v.y, acc.y);
            acc.z = fmaf(sv, v.z, acc.z);
            acc.w = fmaf(sv, v.w, acc.w);
        }
        red4(&g_adj1[k * K1P + off], acc);
    }
    // ---- last-done-block runs the finale ----
    __threadfence();
    __shared__ unsigned s_last;
    if (tid == 0) s_last = (atomicAdd(&g_done, 1u) == gridDim.x - 1) ? 1u : 0u;
    __syncthreads();
    if (!s_last) return;

    __shared__ float sh_adj [K1 * K1];
    __shared__ float sh_adjn[K1 * K1];
    __shared__ float sh_t   [K1 * C1];
    __shared__ float sh_x2  [K1 * C1];
    __shared__ float sh_s2  [K1 * K2];
    __shared__ float sh_as2 [K1 * K2];
    __shared__ float sh_out2[K2 * C1];
    __shared__ float sh_adj2[K2 * K2];
    __shared__ float sh_adj2n[K2 * K2];
    __shared__ float sh_t3  [K2 * C1];
    __shared__ float sh_x3  [K2 * C1];
    __shared__ float sh_d   [K1];
    __shared__ float sh_dg  [K1];
    __shared__ float sh_g   [64];
    __shared__ float sh_fc  [32];

    if (tid < K1) {
        float s = 0.f;
        for (int l = 0; l < K1; l++)
            if (l != tid) s += __ldcg(&g_adj1[tid * K1P + l]);
        sh_d[tid] = sqrtf(s) + EPSF;
    }
    __syncthreads();
    for (int i = tid; i < K1 * K1; i += NT) {
        int k = i / K1, l = i - k * K1;
        sh_adj[i] = (k == l) ? 0.f : __ldcg(&g_adj1[k * K1P + l]) / (sh_d[k] * sh_d[l]);
    }
    __syncthreads();

    if (tid < K1) {
        float s = 1.f;
        for (int l = 0; l < K1; l++) s += sh_adj[tid * K1 + l];
        sh_dg[tid] = rsqrtf(fmaxf(s, 1.f));
    }
    __syncthreads();
    for (int i = tid; i < K1 * K1; i += NT) {
        int k = i / K1, l = i - k * K1;
        float a = sh_adj[i] + ((k == l) ? 1.f : 0.f);
        sh_adjn[i] = a * sh_dg[k] * sh_dg[l];
    }
    for (int i = tid; i < K1 * C1; i += NT) {
        int n = i / C1, f = i - n * C1;
        float a = 0.f;
        for (int c = 0; c < C1; c++)
            a = fmaf(__ldcg(&g_out1[n * C1 + c]), W2[c * C1 + f], a);
        sh_t[i] = a;
    }
    __syncthreads();
    for (int i = tid; i < K1 * C1; i += NT) {
        int n = i / C1, f = i - n * C1;
        float a = b2[f];
        for (int m = 0; m < K1; m++) a = fmaf(sh_adjn[n * K1 + m], sh_t[m * C1 + f], a);
        sh_x2[i] = fmaxf(a, 0.f);
    }
    __syncthreads();

    if (tid < K1) {
        float logit[K2];
        float mx = -1e30f;
        for (int k = 0; k < K2; k++) {
            float a = pb2[k];
            for (int f = 0; f < C1; f++) a = fmaf(sh_x2[tid * C1 + f], pW2[f * K2 + k], a);
            logit[k] = a;
            mx = fmaxf(mx, a);
        }
        float ssum = 0.f;
        for (int k = 0; k < K2; k++) { float e = expf(logit[k] - mx); logit[k] = e; ssum += e; }
        float inv = 1.f / ssum;
        for (int k = 0; k < K2; k++) sh_s2[tid * K2 + k] = logit[k] * inv;
    }
    __syncthreads();

    for (int i = tid; i < K2 * C1; i += NT) {
        int k = i / C1, f = i - k * C1;
        float a = 0.f;
        for (int n = 0; n < K1; n++) a = fmaf(sh_s2[n * K2 + k], sh_x2[n * C1 + f], a);
        sh_out2[i] = a;
    }
    for (int i = tid; i < K1 * K2; i += NT) {
        int n = i / K2, l = i - n * K2;
        float a = 0.f;
        for (int m = 0; m < K1; m++) a = fmaf(sh_adj[n * K1 + m], sh_s2[m * K2 + l], a);
        sh_as2[i] = a;
    }
    __syncthreads();
    for (int i = tid; i < K2 * K2; i += NT) {
        int k = i / K2, l = i - k * K2;
        float a = 0.f;
        for (int n = 0; n < K1; n++) a = fmaf(sh_s2[n * K2 + k], sh_as2[n * K2 + l], a);
        sh_adj2[i] = (k == l) ? 0.f : a;
    }
    __syncthreads();
    if (tid < K2) {
        float s = 0.f;
        for (int l = 0; l < K2; l++) s += sh_adj2[tid * K2 + l];
        sh_d[tid] = sqrtf(s) + EPSF;
    }
    __syncthreads();
    for (int i = tid; i < K2 * K2; i += NT) {
        int k = i / K2, l = i - k * K2;
        sh_adj2[i] = sh_adj2[i] / (sh_d[k] * sh_d[l]);
    }
    __syncthreads();

    if (tid < K2) {
        float s = 1.f;
        for (int l = 0; l < K2; l++) s += sh_adj2[tid * K2 + l];
        sh_dg[tid] = rsqrtf(fmaxf(s, 1.f));
    }
    __syncthreads();
    for (int i = tid; i < K2 * K2; i += NT) {
        int k = i / K2, l = i - k * K2;
        float a = sh_adj2[i] + ((k == l) ? 1.f : 0.f);
        sh_adj2n[i] = a * sh_dg[k] * sh_dg[l];
    }
    for (int i = tid; i < K2 * C1; i += NT) {
        int n = i / C1, f = i - n * C1;
        float a = 0.f;
        for (int c = 0; c < C1; c++) a = fmaf(sh_out2[n * C1 + c], W3[c * C1 + f], a);
        sh_t3[i] = a;
    }
    __syncthreads();
    for (int i = tid; i < K2 * C1; i += NT) {
        int n = i / C1, f = i - n * C1;
        float a = b3[f];
        for (int m = 0; m < K2; m++) a = fmaf(sh_adj2n[n * K2 + m], sh_t3[m * C1 + f], a);
        sh_x3[i] = a;
    }
    __syncthreads();

    if (tid < C1) {
        float s = 0.f;
        for (int n = 0; n < K2; n++) s += sh_x3[n * C1 + tid];
        sh_g[tid]      = s / (float)K2;   // mean
        sh_g[32 + tid] = s;               // sum
    }
    __syncthreads();
    if (tid < 32) {
        float a = l1b[tid];
        for (int i = 0; i < 64; i++) a = fmaf(sh_g[i], l1W[i * 32 + tid], a);
        sh_fc[tid] = fmaxf(a, 0.f);
    }
    __syncthreads();
    if (tid < 2) {
        float a = l2b[tid];
        for (int j = 0; j < 32; j++) a = fmaf(sh_fc[j], l2W[j * 2 + tid], a);
        out[tid] = a;
    }
    if (tid == 0) g_done = 0;            // reset for next replay
}

// ---------------- launch ------------------------------------------------------
template <typename... Args>
static void launch_pdl(void (*kern)(Args...), dim3 grid, dim3 block, Args... args) {
    cudaLaunchConfig_t cfg = {};
    cfg.gridDim = grid;
    cfg.blockDim = block;
    cfg.dynamicSmemBytes = 0;
    cfg.stream = 0;
    cudaLaunchAttribute attr[1];
    attr[0].id = cudaLaunchAttributeProgrammaticStreamSerialization;
    attr[0].val.programmaticStreamSerializationAllowed = 1;
    cfg.attrs = attr;
    cfg.numAttrs = 1;
    cudaLaunchKernelEx(&cfg, kern, args...);
}

extern "C" void kernel_launch(void* const* d_in, const int* in_sizes, int n_in,
                              void* d_out, int out_size) {
    const float* x   = (const float*)d_in[0];
    const int*   ei  = (const int*)  d_in[1];
    const float* W1  = (const float*)d_in[2];
    const float* b1  = (const float*)d_in[3];
    const float* pW1 = (const float*)d_in[4];
    const float* pb1 = (const float*)d_in[5];
    const float* W2  = (const float*)d_in[6];
    const float* b2  = (const float*)d_in[7];
    const float* pW2 = (const float*)d_in[8];
    const float* pb2 = (const float*)d_in[9];
    const float* W3  = (const float*)d_in[10];
    const float* b3  = (const float*)d_in[11];
    const float* l1W = (const float*)d_in[12];
    const float* l1b = (const float*)d_in[13];
    const float* l2W = (const float*)d_in[14];
    const float* l2b = (const float*)d_in[15];
    float* out = (float*)d_out;

    const int N = in_sizes[0] / F_IN;     // 12000
    const int E = in_sizes[1] / 2;        // 192000
    const int* erow = ei;                 // edge_index[0] (sources)
    const int* ecol = ei + E;             // edge_index[1] (targets)

    const int DEG_BLOCKS = (E + 255) / 256;
    const int H_BLOCKS   = (N * 8 + 255) / 256;
    const int AB         = (E * 9 + 319) / 320;   // k_as scatter blocks

    launch_pdl(k0,    dim3(DEG_BLOCKS + H_BLOCKS), dim3(256), ecol, x, W1, E, N, DEG_BLOCKS);
    launch_pdl(k_agg, dim3((E * 8 + 255) / 256), dim3(256), erow, ecol, E);
    launch_pdl(k_s,   dim3((N * 32 + 255) / 256), dim3(256), pW1, pb1, b1, N);
    launch_pdl(k_as,  dim3(AB + RED_BLOCKS), dim3(320), erow, ecol, E, N, AB);
    launch_pdl(k_red, dim3(RED_BLOCKS), dim3(352), N,
               W2, b2, pW2, pb2, W3, b3, l1W, l1b, l2W, l2b, out);
}

// round 12
// speedup vs baseline: 1.7289x; 1.7289x over previous
#include <cuda_runtime.h>
#include <math.h>

#define NMAX   12000
#define F_IN   10
#define C1     32
#define K1     35
#define K1P    36          // padded stride for s / as (144B, 16B-aligned)
#define K2     18
#define EPSF   1e-15f
#define RED_BLOCKS 120

// ---------------- device scratch (static: zero at module load) ---------------
__device__ __align__(16) float g_dis[NMAX];          // D^-1/2
__device__ __align__(16) float g_degf[NMAX];         // degree count (self-cleaned in k_s)
__device__ __align__(16) float g_hn [NMAX * C1];     // dis*(xW1), then h1
__device__ __align__(16) float g_acc[NMAX * C1];     // scatter accumulator
__device__ __align__(16) float g_s  [NMAX * K1P];    // softmax assignments (padded)
__device__ __align__(16) float g_as [NMAX * K1P];    // adj @ s (zeroed per-row in k_s)
__device__ __align__(16) float g_out1[K1 * C1];      // s^T h1   (zeroed in k_s blk0)
__device__ __align__(16) float g_adj1[K1 * K1P];     // s^T a_s  (zeroed in k_s blk0)
__device__ unsigned g_done;                          // k_red completion counter

__device__ __forceinline__ void red4(float* p, float4 v) {
    asm volatile("red.global.add.v4.f32 [%0], {%1,%2,%3,%4};"
                 :: "l"(p), "f"(v.x), "f"(v.y), "f"(v.z), "f"(v.w) : "memory");
}

// ---------------- kernels ----------------------------------------------------

// degree-only first kernel (g_degf pre-zeroed by k_s of prior replay)
__global__ void k_deg(const int* __restrict__ col, int E) {
    int e = blockIdx.x * blockDim.x + threadIdx.x;
    if (e < E) atomicAdd(&g_degf[col[e]], 1.0f);
}

// dis = (deg+1)^-1/2 ; hn = dis*(x@W1) ; acc = hn.  8 threads/node, float4 out.
__global__ void k_h(const float* __restrict__ x, const float* __restrict__ W1, int N) {
    __shared__ float sW[F_IN * C1];
    for (int j = threadIdx.x; j < F_IN * C1; j += blockDim.x) sW[j] = W1[j];   // prologue
    __syncthreads();
    cudaGridDependencySynchronize();
    int t = blockIdx.x * blockDim.x + threadIdx.x;
    int i = t >> 3;
    int q = (t & 7) << 2;          // feature group base
    if (i >= N) return;
    float dis = rsqrtf(g_degf[i] + 1.0f);
    if (q == 0) g_dis[i] = dis;
    float xv[F_IN];
    #pragma unroll
    for (int d = 0; d < F_IN; d++) xv[d] = __ldg(&x[i * F_IN + d]);
    float4 v;
    float* vp = (float*)&v;
    #pragma unroll
    for (int j = 0; j < 4; j++) {
        float a = 0.f;
        #pragma unroll
        for (int d = 0; d < F_IN; d++) a = fmaf(xv[d], sW[d * C1 + q + j], a);
        vp[j] = dis * a;
    }
    *(float4*)&g_hn [i * C1 + q] = v;
    *(float4*)&g_acc[i * C1 + q] = v;
}

// acc[col] += hn[row] per edge: 8 threads/edge, one float4 + one red.v4 each
__global__ void k_agg(const int* __restrict__ row, const int* __restrict__ col, int E) {
    int t = blockIdx.x * blockDim.x + threadIdx.x;
    int e = t >> 3;
    int q = (t & 7) << 2;
    if (e >= E) return;
    int r = __ldg(&row[e]);            // indices independent of k_h
    int c = __ldg(&col[e]);
    cudaGridDependencySynchronize();
    float4 v = *(const float4*)&g_hn[r * C1 + q];
    red4(&g_acc[c * C1 + q], v);
}

// h1 = relu(dis*acc + b1); s = softmax(h1 @ pW1 + pb1).  WARP PER NODE.
// Also zeroes g_as row (before k_as) and out1/adj1 (block 0, before k_red).
__global__ void k_s(const float* __restrict__ pW1, const float* __restrict__ pb1,
                    const float* __restrict__ b1, int N) {
    __shared__ float sW[C1 * K1P];     // padded: col 35 = 0
    __shared__ float sb[K1P];          // pad bias = -1e30
    __shared__ float sb1[C1];
    for (int j = threadIdx.x; j < C1 * K1P; j += blockDim.x) {
        int f = j / K1P, k = j - f * K1P;
        sW[j] = (k < K1) ? pW1[f * K1 + k] : 0.f;
    }
    if (threadIdx.x < K1P) sb[threadIdx.x] = (threadIdx.x < K1) ? pb1[threadIdx.x] : -1e30f;
    if (threadIdx.x < C1)  sb1[threadIdx.x] = b1[threadIdx.x];
    __syncthreads();
    cudaGridDependencySynchronize();
    // block 0: zero the pooled-reduction targets (consumed 1-2 kernels later)
    if (blockIdx.x == 0) {
        for (int j = threadIdx.x; j < K1 * C1;  j += blockDim.x) g_out1[j] = 0.f;
        for (int j = threadIdx.x; j < K1 * K1P; j += blockDim.x) g_adj1[j] = 0.f;
    }
    const int lane = threadIdx.x & 31;
    const int i = (blockIdx.x * blockDim.x + threadIdx.x) >> 5;
    if (i >= N) return;
    // zero this node's a_s row (before k_as REDs, ordered by PDL chain)
    if (lane < 9) *(float4*)&g_as[i * K1P + (lane << 2)] =
        make_float4(0.f, 0.f, 0.f, 0.f);
    const float dis = g_dis[i];
    // h[lane]
    float hv = fmaxf(fmaf(dis, g_acc[i * C1 + lane], sb1[lane]), 0.f);
    g_hn[i * C1 + lane] = hv;
    // logits via shfl broadcast of h
    const int k1 = 32 + (lane & 3);     // duplicated across lane groups; only lane<4 writes
    float lg0 = sb[lane];
    float lg1 = sb[k1];
    #pragma unroll
    for (int f = 0; f < C1; f++) {
        float hf = __shfl_sync(0xffffffffu, hv, f);
        lg0 = fmaf(hf, sW[f * K1P + lane], lg0);
        lg1 = fmaf(hf, sW[f * K1P + k1],  lg1);
    }
    float m = fmaxf(lg0, lg1);
    #pragma unroll
    for (int o = 16; o; o >>= 1) m = fmaxf(m, __shfl_xor_sync(0xffffffffu, m, o));
    float e0 = expf(lg0 - m);
    float e1 = expf(lg1 - m);           // k=35 pad: exp(-huge) = 0
    float ssum = e0 + ((lane < 4) ? e1 : 0.f);
    #pragma unroll
    for (int o = 16; o; o >>= 1) ssum += __shfl_xor_sync(0xffffffffu, ssum, o);
    float inv = 1.f / ssum;
    g_s[i * K1P + lane] = e0 * inv;
    if (lane < 4) g_s[i * K1P + 32 + lane] = e1 * inv;   // lane3 -> pad col = 0
    if (lane == 0) g_degf[i] = 0.f;     // self-clean for next replay
}

// a_s[row] += s[col] per edge: 9 threads/edge (36 padded cols / 4)
__global__ void k_as(const int* __restrict__ row, const int* __restrict__ col, int E) {
    int t = blockIdx.x * blockDim.x + threadIdx.x;
    int e = t / 9;
    int q = (t - e * 9) << 2;
    int r = 0, c = 0;
    if (e < E) {                        // index loads independent of k_s: prologue
        r = __ldg(&row[e]);
        c = __ldg(&col[e]);
    }
    cudaGridDependencySynchronize();
    if (e >= E) return;
    float4 v = *(const float4*)&g_s[c * K1P + q];
    red4(&g_as[r * K1P + q], v);
}

// out1 = s^T h1 ; adj1 = s^T as  (partial per block + red4), then the LAST
// block to finish runs the entire post-pool finale inline (threadfence pattern).
__global__ void k_red(int N,
                      const float* __restrict__ W2,  const float* __restrict__ b2,
                      const float* __restrict__ pW2, const float* __restrict__ pb2,
                      const float* __restrict__ W3,  const float* __restrict__ b3,
                      const float* __restrict__ l1W, const float* __restrict__ l1b,
                      const float* __restrict__ l2W, const float* __restrict__ l2b,
                      float* __restrict__ out) {
    cudaGridDependencySynchronize();
    const int tid = threadIdx.x;
    const int NT  = blockDim.x;
    {
        const int k  = tid / 17;
        const int jg = tid - k * 17;
        int per = (N + gridDim.x - 1) / gridDim.x;
        int n0 = blockIdx.x * per;
        int n1 = min(n0 + per, N);
        if (tid < K1 * 17) {
            const bool is_h = (jg < 8);
            const int off = is_h ? (jg << 2) : ((jg - 8) << 2);
            float4 acc = make_float4(0.f, 0.f, 0.f, 0.f);
            for (int n = n0; n < n1; n++) {
                float sv = __ldg(&g_s[n * K1P + k]);
                float4 v = is_h ? *(const float4*)&g_hn[n * C1  + off]
                                : *(const float4*)&g_as[n * K1P + off];
                acc.x = fmaf(sv, v.x, acc.x);
                acc.y = fmaf(sv, v.y, acc.y);
                acc.z = fmaf(sv, v.z, acc.z);
                acc.w = fmaf(sv, v.w, acc.w);
            }
            if (is_h) red4(&g_out1[k * C1  + off], acc);
            else      red4(&g_adj1[k * K1P + off], acc);
        }
    }
    // ---- last-done-block runs the finale ----
    __threadfence();                    // REDs visible in L2 before the count
    __shared__ unsigned s_last;
    if (tid == 0) s_last = (atomicAdd(&g_done, 1u) == gridDim.x - 1) ? 1u : 0u;
    __syncthreads();
    if (!s_last) return;

    __shared__ float sh_adj [K1 * K1];
    __shared__ float sh_adjn[K1 * K1];
    __shared__ float sh_t   [K1 * C1];
    __shared__ float sh_x2  [K1 * C1];
    __shared__ float sh_s2  [K1 * K2];
    __shared__ float sh_as2 [K1 * K2];
    __shared__ float sh_out2[K2 * C1];
    __shared__ float sh_adj2[K2 * K2];
    __shared__ float sh_adj2n[K2 * K2];
    __shared__ float sh_t3  [K2 * C1];
    __shared__ float sh_x3  [K2 * C1];
    __shared__ float sh_d   [K1];
    __shared__ float sh_dg  [K1];
    __shared__ float sh_g   [64];
    __shared__ float sh_fc  [32];

    // pool-1 adjacency normalization: diag 0, d = sqrt(rowsum)+eps
    if (tid < K1) {
        float s = 0.f;
        for (int l = 0; l < K1; l++)
            if (l != tid) s += __ldcg(&g_adj1[tid * K1P + l]);
        sh_d[tid] = sqrtf(s) + EPSF;
    }
    __syncthreads();
    for (int i = tid; i < K1 * K1; i += NT) {
        int k = i / K1, l = i - k * K1;
        sh_adj[i] = (k == l) ? 0.f : __ldcg(&g_adj1[k * K1P + l]) / (sh_d[k] * sh_d[l]);
    }
    __syncthreads();

    // DenseGCNConv(W2): diag=1, deg=max(sum,1)^-1/2, relu
    if (tid < K1) {
        float s = 1.f;
        for (int l = 0; l < K1; l++) s += sh_adj[tid * K1 + l];
        sh_dg[tid] = rsqrtf(fmaxf(s, 1.f));
    }
    __syncthreads();
    for (int i = tid; i < K1 * K1; i += NT) {
        int k = i / K1, l = i - k * K1;
        float a = sh_adj[i] + ((k == l) ? 1.f : 0.f);
        sh_adjn[i] = a * sh_dg[k] * sh_dg[l];
    }
    for (int i = tid; i < K1 * C1; i += NT) {
        int n = i / C1, f = i - n * C1;
        float a = 0.f;
        for (int c = 0; c < C1; c++)
            a = fmaf(__ldcg(&g_out1[n * C1 + c]), W2[c * C1 + f], a);
        sh_t[i] = a;
    }
    __syncthreads();
    for (int i = tid; i < K1 * C1; i += NT) {
        int n = i / C1, f = i - n * C1;
        float a = b2[f];
        for (int m = 0; m < K1; m++) a = fmaf(sh_adjn[n * K1 + m], sh_t[m * C1 + f], a);
        sh_x2[i] = fmaxf(a, 0.f);
    }
    __syncthreads();

    // s2 = softmax(x2 @ pW2 + pb2)
    if (tid < K1) {
        float logit[K2];
        float mx = -1e30f;
        for (int k = 0; k < K2; k++) {
            float a = pb2[k];
            for (int f = 0; f < C1; f++) a = fmaf(sh_x2[tid * C1 + f], pW2[f * K2 + k], a);
            logit[k] = a;
            mx = fmaxf(mx, a);
        }
        float ssum = 0.f;
        for (int k = 0; k < K2; k++) { float e = expf(logit[k] - mx); logit[k] = e; ssum += e; }
        float inv = 1.f / ssum;
        for (int k = 0; k < K2; k++) sh_s2[tid * K2 + k] = logit[k] * inv;
    }
    __syncthreads();

    // pool 2
    for (int i = tid; i < K2 * C1; i += NT) {
        int k = i / C1, f = i - k * C1;
        float a = 0.f;
        for (int n = 0; n < K1; n++) a = fmaf(sh_s2[n * K2 + k], sh_x2[n * C1 + f], a);
        sh_out2[i] = a;
    }
    for (int i = tid; i < K1 * K2; i += NT) {
        int n = i / K2, l = i - n * K2;
        float a = 0.f;
        for (int m = 0; m < K1; m++) a = fmaf(sh_adj[n * K1 + m], sh_s2[m * K2 + l], a);
        sh_as2[i] = a;
    }
    __syncthreads();
    for (int i = tid; i < K2 * K2; i += NT) {
        int k = i / K2, l = i - k * K2;
        float a = 0.f;
        for (int n = 0; n < K1; n++) a = fmaf(sh_s2[n * K2 + k], sh_as2[n * K2 + l], a);
        sh_adj2[i] = (k == l) ? 0.f : a;
    }
    __syncthreads();
    if (tid < K2) {
        float s = 0.f;
        for (int l = 0; l < K2; l++) s += sh_adj2[tid * K2 + l];
        sh_d[tid] = sqrtf(s) + EPSF;
    }
    __syncthreads();
    for (int i = tid; i < K2 * K2; i += NT) {
        int k = i / K2, l = i - k * K2;
        sh_adj2[i] = sh_adj2[i] / (sh_d[k] * sh_d[l]);
    }
    __syncthreads();

    // DenseGCNConv(W3), no relu
    if (tid < K2) {
        float s = 1.f;
        for (int l = 0; l < K2; l++) s += sh_adj2[tid * K2 + l];
        sh_dg[tid] = rsqrtf(fmaxf(s, 1.f));
    }
    __syncthreads();
    for (int i = tid; i < K2 * K2; i += NT) {
        int k = i / K2, l = i - k * K2;
        float a = sh_adj2[i] + ((k == l) ? 1.f : 0.f);
        sh_adj2n[i] = a * sh_dg[k] * sh_dg[l];
    }
    for (int i = tid; i < K2 * C1; i += NT) {
        int n = i / C1, f = i - n * C1;
        float a = 0.f;
        for (int c = 0; c < C1; c++) a = fmaf(sh_out2[n * C1 + c], W3[c * C1 + f], a);
        sh_t3[i] = a;
    }
    __syncthreads();
    for (int i = tid; i < K2 * C1; i += NT) {
        int n = i / C1, f = i - n * C1;
        float a = b3[f];
        for (int m = 0; m < K2; m++) a = fmaf(sh_adj2n[n * K2 + m], sh_t3[m * C1 + f], a);
        sh_x3[i] = a;
    }
    __syncthreads();

    // readout + MLP
    if (tid < C1) {
        float s = 0.f;
        for (int n = 0; n < K2; n++) s += sh_x3[n * C1 + tid];
        sh_g[tid]      = s / (float)K2;   // mean
        sh_g[32 + tid] = s;               // sum
    }
    __syncthreads();
    if (tid < 32) {
        float a = l1b[tid];
        for (int i = 0; i < 64; i++) a = fmaf(sh_g[i], l1W[i * 32 + tid], a);
        sh_fc[tid] = fmaxf(a, 0.f);
    }
    __syncthreads();
    if (tid < 2) {
        float a = l2b[tid];
        for (int j = 0; j < 32; j++) a = fmaf(sh_fc[j], l2W[j * 2 + tid], a);
        out[tid] = a;
    }
    if (tid == 0) g_done = 0;            // reset for next replay
}

// ---------------- launch ------------------------------------------------------
template <typename... Args>
static void launch_pdl(void (*kern)(Args...), dim3 grid, dim3 block, Args... args) {
    cudaLaunchConfig_t cfg = {};
    cfg.gridDim = grid;
    cfg.blockDim = block;
    cfg.dynamicSmemBytes = 0;
    cfg.stream = 0;
    cudaLaunchAttribute attr[1];
    attr[0].id = cudaLaunchAttributeProgrammaticStreamSerialization;
    attr[0].val.programmaticStreamSerializationAllowed = 1;
    cfg.attrs = attr;
    cfg.numAttrs = 1;
    cudaLaunchKernelEx(&cfg, kern, args...);
}

extern "C" void kernel_launch(void* const* d_in, const int* in_sizes, int n_in,
                              void* d_out, int out_size) {
    const float* x   = (const float*)d_in[0];
    const int*   ei  = (const int*)  d_in[1];
    const float* W1  = (const float*)d_in[2];
    const float* b1  = (const float*)d_in[3];
    const float* pW1 = (const float*)d_in[4];
    const float* pb1 = (const float*)d_in[5];
    const float* W2  = (const float*)d_in[6];
    const float* b2  = (const float*)d_in[7];
    const float* pW2 = (const float*)d_in[8];
    const float* pb2 = (const float*)d_in[9];
    const float* W3  = (const float*)d_in[10];
    const float* b3  = (const float*)d_in[11];
    const float* l1W = (const float*)d_in[12];
    const float* l1b = (const float*)d_in[13];
    const float* l2W = (const float*)d_in[14];
    const float* l2b = (const float*)d_in[15];
    float* out = (float*)d_out;

    const int N = in_sizes[0] / F_IN;     // 12000
    const int E = in_sizes[1] / 2;        // 192000
    const int* erow = ei;                 // edge_index[0] (sources)
    const int* ecol = ei + E;             // edge_index[1] (targets)

    launch_pdl(k_deg, dim3((E + 255) / 256), dim3(256), ecol, E);
    launch_pdl(k_h,   dim3((N * 8 + 255) / 256), dim3(256), x, W1, N);
    launch_pdl(k_agg, dim3((E * 8 + 255) / 256), dim3(256), erow, ecol, E);
    launch_pdl(k_s,   dim3((N * 32 + 255) / 256), dim3(256), pW1, pb1, b1, N);
    launch_pdl(k_as,  dim3((E * 9 + 255) / 256), dim3(256), erow, ecol, E);
    launch_pdl(k_red, dim3(RED_BLOCKS), dim3(608), N,
               W2, b2, pW2, pb2, W3, b3, l1W, l1b, l2W, l2b, out);
}